// round 13
// baseline (speedup 1.0000x reference)
#include <cuda_runtime.h>
#include <math.h>

#define Bv   4
#define Tv   64
#define Nv   1024
#define Ev   16384
#define Cv   32
#define T1v  62
#define T2v  60

// ---- device scratch (referenced only from device code) ----
__device__ float g_h1[Bv * T1v * Nv * Cv];
__device__ float g_hc[Bv * T1v * Nv * Cv];
__device__ float g_h2[Bv * T2v * Nv * Cv];
__device__ float g_y0[Bv * T1v * Nv * Cv];   // h1 @ W0
__device__ float g_y1[Bv * T1v * Nv * Cv];   // h1 @ W1
__device__ float g_wT[2][3][3072];           // [layer][gate][r*32+co], r=ci*3+k
__device__ int   g_rowptr[Nv + 1];
__device__ int   g_col[Ev];                  // pre-multiplied by 32
__device__ float g_val[Ev];

// ---- f32x2 helpers ----
__device__ __forceinline__ unsigned long long fma2(unsigned long long a,
                                                   unsigned long long b,
                                                   unsigned long long c) {
    unsigned long long d;
    asm("fma.rn.f32x2 %0, %1, %2, %3;" : "=l"(d) : "l"(a), "l"(b), "l"(c));
    return d;
}
__device__ __forceinline__ unsigned long long dup2(float x) {
    unsigned long long d;
    unsigned u = __float_as_uint(x);
    asm("mov.b64 %0, {%1, %1};" : "=l"(d) : "r"(u));
    return d;
}
__device__ __forceinline__ void unpack2(unsigned long long v, float& lo, float& hi) {
    unsigned a, b;
    asm("mov.b64 {%0, %1}, %2;" : "=r"(a), "=r"(b) : "l"(v));
    lo = __uint_as_float(a);
    hi = __uint_as_float(b);
}

__device__ __forceinline__ void load_edge_f(const void* ei, int e, int is64,
                                            int& s, int& d) {
    if (is64) {
        const long long* e64 = (const long long*)ei;
        s = (int)e64[e]; d = (int)e64[Ev + e];
    } else {
        const int* e32 = (const int*)ei;
        s = e32[e]; d = e32[Ev + e];
    }
}

// ------------------------------------------------------------------
// Prep 1/2: weight reshuffle, one layer each (12 blocks x 256).
// ------------------------------------------------------------------
__global__ void prep_w_kernel(const float* __restrict__ wa, const float* __restrict__ wb,
                              const float* __restrict__ wc, int layer) {
    int i = blockIdx.x * blockDim.x + threadIdx.x;
    if (i >= 3072) return;
    int r = i >> 5, co = i & 31;
    int s = co * 96 + r;
    g_wT[layer][0][i] = wa[s];
    g_wT[layer][1][i] = wb[s];
    g_wT[layer][2][i] = wc[s];
}

// ------------------------------------------------------------------
// Prep 3: graph build (single block, 1024 threads, smem-resident).
// ------------------------------------------------------------------
__global__ void prep_graph_kernel(const void* __restrict__ ei,
                                  const float* __restrict__ ew) {
    __shared__ float sdeg[Nv];
    __shared__ int   scnt[Nv];
    __shared__ int   sscan[Nv];
    __shared__ int   soffs[Nv];
    __shared__ int   sOr;

    const int i = threadIdx.x;
    if (i == 0) sOr = 0;
    sdeg[i] = 0.f;
    scnt[i] = 0;
    __syncthreads();

    if (i < 128) {
        int v = ((const int*)ei)[2 * i + 1];
        if (v != 0) atomicOr(&sOr, 1);
    }
    __syncthreads();
    const int is64 = (sOr == 0) ? 1 : 0;

    for (int e = i; e < Ev; e += 1024) {
        int s, d;
        load_edge_f(ei, e, is64, s, d);
        if ((unsigned)s >= Nv || (unsigned)d >= Nv) continue;
        float w = ew[e];
        if (s != d) atomicAdd(&sdeg[s], w);
        atomicAdd(&scnt[d], 1);
    }
    __syncthreads();

    {
        float dg = sdeg[i];
        float dv = (dg > 0.f) ? rsqrtf(dg) : 0.f;
        __syncthreads();
        sdeg[i] = dv;
    }

    int c = scnt[i];
    sscan[i] = c;
    for (int off = 1; off < Nv; off <<= 1) {
        __syncthreads();
        int v = (i >= off) ? sscan[i - off] : 0;
        __syncthreads();
        sscan[i] += v;
    }
    __syncthreads();
    int excl = sscan[i] - c;
    g_rowptr[i] = excl;
    soffs[i]    = excl;
    if (i == Nv - 1) g_rowptr[Nv] = sscan[i];
    __syncthreads();

    for (int e = i; e < Ev; e += 1024) {
        int s, d;
        load_edge_f(ei, e, is64, s, d);
        if ((unsigned)s >= Nv || (unsigned)d >= Nv) continue;
        float w = ew[e];
        float nrm = (s == d) ? 0.f : (-sdeg[s] * w * sdeg[d]);
        int pos = atomicAdd(&soffs[d], 1);
        if ((unsigned)pos < Ev) {
            g_col[pos] = s * 32;        // pre-multiplied row offset
            g_val[pos] = nrm;
        }
    }
}

// ------------------------------------------------------------------
// Temporal gated conv with explicit 2-stage register pipeline.
// Block 256 thr, tile 128n x 32co. Warp wg: 4 co; lane: 4 consecutive n.
// Flattened it = k*32+ci (0..95); per-iter: prefetch next x/w while
// issuing 24 FFMA2 of current iter.
// ------------------------------------------------------------------
#define WS_FLOATS (3 * 96 * 32)    // 9216
#define XS_FLOATS (3 * 32 * 128)   // 12288
#define TC_SMEM   ((WS_FLOATS + XS_FLOATS) * 4)

__global__ __launch_bounds__(256, 2)
void tconv_kernel(const float* __restrict__ xp,
                  const float* __restrict__ b1, const float* __restrict__ b2,
                  const float* __restrict__ b3,
                  int layer, int src_sel, int dst_sel, int Tin, int Tout)
{
    extern __shared__ __align__(16) float sm[];
    float* ws = sm;
    float* xs = sm + WS_FLOATS;

    const float* x   = (src_sel == 0) ? xp   : (const float*)g_hc;
    float*       out = (dst_sel == 0) ? g_h1 : g_h2;

    const int tid = threadIdx.x;
    const int n0  = blockIdx.x * 128;
    const int t   = blockIdx.y;
    const int b   = blockIdx.z;

    {
        const float* wsrc = &g_wT[layer][0][0];
        for (int i = tid; i < WS_FLOATS; i += 256) ws[i] = wsrc[i];
    }
    {
        const float* xb = x + ((long long)(b * Tin + t) * Nv + n0) * Cv;
        for (int idx = tid; idx < XS_FLOATS; idx += 256) {
            int k   = idx >> 12;
            int rem = idx & 4095;
            int n   = rem >> 5;
            int ci  = rem & 31;
            int rx  = k * 32 + ci;
            xs[rx * 128 + (((n >> 2) ^ ci) << 2) + (n & 3)] =
                xb[(long long)k * Nv * Cv + rem];
        }
    }
    __syncthreads();

    const int wg   = tid >> 5;
    const int lane = tid & 31;

    unsigned long long acc[3][8];
#pragma unroll
    for (int g = 0; g < 3; ++g)
#pragma unroll
        for (int i = 0; i < 8; ++i) acc[g][i] = 0ull;

    // prologue: iter 0 (it = rx = k*32+ci; ci=it&31, k=it>>5; rw=ci*3+k)
    float4     xv = *(const float4*)(xs + ((lane ^ 0) << 2));
    ulonglong2 wa = *(const ulonglong2*)(ws +        wg * 4);
    ulonglong2 wb = *(const ulonglong2*)(ws + 3072 + wg * 4);
    ulonglong2 wc = *(const ulonglong2*)(ws + 6144 + wg * 4);

#pragma unroll 2
    for (int it = 0; it < 96; ++it) {
        float4     xvn;
        ulonglong2 wan, wbn, wcn;
        if (it < 95) {
            const int itn = it + 1;
            const int cin = itn & 31;
            const int kn  = itn >> 5;
            xvn = *(const float4*)(xs + itn * 128 + ((lane ^ cin) << 2));
            const float* wp = ws + (cin * 3 + kn) * 32 + wg * 4;
            wan = *(const ulonglong2*)(wp);
            wbn = *(const ulonglong2*)(wp + 3072);
            wcn = *(const ulonglong2*)(wp + 6144);
        }
        unsigned long long xp2[4];
        xp2[0] = dup2(xv.x); xp2[1] = dup2(xv.y);
        xp2[2] = dup2(xv.z); xp2[3] = dup2(xv.w);
#pragma unroll
        for (int i = 0; i < 4; ++i) {
            acc[0][i * 2 + 0] = fma2(xp2[i], wa.x, acc[0][i * 2 + 0]);
            acc[0][i * 2 + 1] = fma2(xp2[i], wa.y, acc[0][i * 2 + 1]);
            acc[1][i * 2 + 0] = fma2(xp2[i], wb.x, acc[1][i * 2 + 0]);
            acc[1][i * 2 + 1] = fma2(xp2[i], wb.y, acc[1][i * 2 + 1]);
            acc[2][i * 2 + 0] = fma2(xp2[i], wc.x, acc[2][i * 2 + 0]);
            acc[2][i * 2 + 1] = fma2(xp2[i], wc.y, acc[2][i * 2 + 1]);
        }
        xv = xvn; wa = wan; wb = wbn; wc = wcn;
    }
    __syncthreads();

    const int nn = lane * 4;
#pragma unroll
    for (int p = 0; p < 2; ++p) {
        const int co0 = wg * 4 + p * 2;
        const float b1a = b1[co0], b1b = b1[co0 + 1];
        const float b2a = b2[co0], b2b = b2[co0 + 1];
        const float b3a = b3[co0], b3b = b3[co0 + 1];
#pragma unroll
        for (int i = 0; i < 4; ++i) {
            float p0, p1, q0, q1, r0, r1;
            unpack2(acc[0][i * 2 + p], p0, p1);
            unpack2(acc[1][i * 2 + p], q0, q1);
            unpack2(acc[2][i * 2 + p], r0, r1);
            p0 += b1a; p1 += b1b;
            q0 += b2a; q1 += b2b;
            r0 += b3a; r1 += b3b;
            float s0 = 1.f / (1.f + __expf(-q0));
            float s1 = 1.f / (1.f + __expf(-q1));
            float h0 = p0 * s0 + r0;
            float h1 = p1 * s1 + r1;
            xs[(nn + i) * 33 + co0]     = (h0 > 0.f) ? h0 : 0.f;
            xs[(nn + i) * 33 + co0 + 1] = (h1 > 0.f) ? h1 : 0.f;
        }
    }
    __syncthreads();

    float* ob = out + ((long long)(b * Tout + t) * Nv + n0) * Cv;
    for (int idx = tid; idx < 4096; idx += 256) {
        ob[idx] = xs[(idx >> 5) * 33 + (idx & 31)];
    }
}

// ------------------------------------------------------------------
// Cheb GEMM: Y0 = h1 @ W0, Y1 = h1 @ W1 (proven R12 version).
// ------------------------------------------------------------------
#define CG_SMEM 33792

__global__ __launch_bounds__(256)
void cheb_gemm_kernel(const float* __restrict__ W)   // [2][32][32]
{
    extern __shared__ __align__(16) float sm[];
    float* ws = sm;                     // [k][64] plain floats
    float* xs = sm + 2048;              // 4096 floats

    const int tid = threadIdx.x;
    const int n0  = blockIdx.x * 128;
    const int t   = blockIdx.y;
    const int b   = blockIdx.z;

    for (int i = tid; i < 2048; i += 256) {
        int k = i >> 6, o = i & 63;
        ws[i] = (o < 32) ? W[k * 32 + o] : W[1024 + k * 32 + (o - 32)];
    }
    {
        const float* xb = g_h1 + ((long long)(b * T1v + t) * Nv + n0) * Cv;
        for (int idx = tid; idx < 4096; idx += 256) {
            int n = idx >> 5, c = idx & 31;
            xs[c * 128 + (((n >> 2) ^ c) << 2) + (n & 3)] = xb[idx];
        }
    }
    __syncthreads();

    const int wg   = tid >> 5;
    const int lane = tid & 31;

    unsigned long long acc[16];
#pragma unroll
    for (int i = 0; i < 16; ++i) acc[i] = 0ull;

#pragma unroll 8
    for (int k = 0; k < 32; ++k) {
        const float4 xv4 = *(const float4*)(xs + k * 128 + ((lane ^ k) << 2));
        unsigned long long xp2[4];
        xp2[0] = dup2(xv4.x); xp2[1] = dup2(xv4.y);
        xp2[2] = dup2(xv4.z); xp2[3] = dup2(xv4.w);
        const float* wrow = ws + k * 64 + wg * 8;
        const ulonglong2 w01 = *(const ulonglong2*)(wrow);
        const ulonglong2 w23 = *(const ulonglong2*)(wrow + 4);
#pragma unroll
        for (int i = 0; i < 4; ++i) {
            acc[i * 4 + 0] = fma2(xp2[i], w01.x, acc[i * 4 + 0]);
            acc[i * 4 + 1] = fma2(xp2[i], w01.y, acc[i * 4 + 1]);
            acc[i * 4 + 2] = fma2(xp2[i], w23.x, acc[i * 4 + 2]);
            acc[i * 4 + 3] = fma2(xp2[i], w23.y, acc[i * 4 + 3]);
        }
    }
    __syncthreads();

    float* stg = sm;    // [128][66]
    const int nn = lane * 4;
#pragma unroll
    for (int i = 0; i < 4; ++i) {
#pragma unroll
        for (int p = 0; p < 4; ++p) {
            float lo, hi;
            unpack2(acc[i * 4 + p], lo, hi);
            *(float2*)(stg + (nn + i) * 66 + wg * 8 + p * 2) = make_float2(lo, hi);
        }
    }
    __syncthreads();

    const long long base = (long long)(b * T1v + t) * Nv * Cv + (long long)n0 * Cv;
    for (int idx = tid; idx < 4096; idx += 256) {
        int n = idx >> 5, c = idx & 31;
        g_y0[base + idx] = stg[n * 66 + c];
        g_y1[base + idx] = stg[n * 66 + 32 + c];
    }
}

// ------------------------------------------------------------------
// Cheb gather: out = relu(Y0[n] + cb + sum_e norm * Y1[src]).
// Warp per node, 4 t-planes; g_col pre-multiplied by 32.
// ------------------------------------------------------------------
__global__ __launch_bounds__(256)
void cheb_gather_kernel(const float* __restrict__ cbias)
{
    const int tid  = threadIdx.x;
    const int w    = tid >> 5;
    const int lane = tid & 31;
    const int b    = blockIdx.z;
    const int n    = blockIdx.x * 8 + w;
    const int t0   = blockIdx.y * 4;
    const int TC   = (t0 + 4 <= T1v) ? 4 : (T1v - t0);

    const float cb = __ldg(&cbias[lane]);
    const int e0 = g_rowptr[n], e1 = g_rowptr[n + 1];
    const long long stride = (long long)Nv * Cv;
    const float* base1 = g_y1 + (long long)(b * T1v + t0) * stride;
    const float* base0 = g_y0 + (long long)(b * T1v + t0) * stride;

    float lh[4] = {0.f, 0.f, 0.f, 0.f};

    int e = e0;
    for (; e + 2 <= e1; e += 2) {
        int   cA = g_col[e],   cB = g_col[e + 1];     // already *32
        float vA = g_val[e],   vB = g_val[e + 1];
        const float* pA = base1 + cA + lane;
        const float* pB = base1 + cB + lane;
#pragma unroll
        for (int j = 0; j < 4; ++j) {
            if (j < TC) {
                lh[j] = fmaf(vA, pA[j * stride], lh[j]);
                lh[j] = fmaf(vB, pB[j * stride], lh[j]);
            }
        }
    }
    if (e < e1) {
        int   cA = g_col[e];
        float vA = g_val[e];
        const float* pA = base1 + cA + lane;
#pragma unroll
        for (int j = 0; j < 4; ++j)
            if (j < TC) lh[j] = fmaf(vA, pA[j * stride], lh[j]);
    }

    float* outb = g_hc + (long long)(b * T1v + t0) * stride + n * 32 + lane;
#pragma unroll
    for (int j = 0; j < 4; ++j) {
        if (j < TC) {
            float o = base0[j * stride + n * 32 + lane] + cb + lh[j];
            outb[j * stride] = (o > 0.f) ? o : 0.f;
        }
    }
}

// ------------------------------------------------------------------
// BatchNorm per node over (B, T2, C).
// ------------------------------------------------------------------
__global__ __launch_bounds__(256)
void bn_kernel(const float* __restrict__ gamma, const float* __restrict__ beta,
               float* __restrict__ outp)
{
    __shared__ float rs[256], rs2[256];
    __shared__ float s_scale, s_shift;
    const int n = blockIdx.x, tid = threadIdx.x;
    const int M = Bv * T2v * Cv;

    float s = 0.f, s2 = 0.f;
    for (int i = tid; i < M; i += 256) {
        int row = i >> 5, c = i & 31;
        float v = g_h2[((long long)row * Nv + n) * 32 + c];
        s += v; s2 += v * v;
    }
    rs[tid] = s; rs2[tid] = s2;
    __syncthreads();
    for (int off = 128; off > 0; off >>= 1) {
        if (tid < off) { rs[tid] += rs[tid + off]; rs2[tid] += rs2[tid + off]; }
        __syncthreads();
    }
    if (tid == 0) {
        float mean = rs[0] / (float)M;
        float var  = rs2[0] / (float)M - mean * mean;
        float rstd = rsqrtf(var + 1e-5f);
        float sc = gamma[n] * rstd;
        s_scale = sc;
        s_shift = beta[n] - mean * sc;
    }
    __syncthreads();
    const float sc = s_scale, sf = s_shift;
    for (int i = tid; i < M; i += 256) {
        int row = i >> 5, c = i & 31;
        long long idx = ((long long)row * Nv + n) * 32 + c;
        outp[idx] = g_h2[idx] * sc + sf;
    }
}

// ------------------------------------------------------------------
extern "C" void kernel_launch(void* const* d_in, const int* in_sizes, int n_in,
                              void* d_out, int out_size)
{
    const float* x   = (const float*)d_in[0];
    const void*  ei  = d_in[1];
    const float* ew  = (const float*)d_in[2];
    const float* w11 = (const float*)d_in[3];
    const float* b11 = (const float*)d_in[4];
    const float* w12 = (const float*)d_in[5];
    const float* b12 = (const float*)d_in[6];
    const float* w13 = (const float*)d_in[7];
    const float* b13 = (const float*)d_in[8];
    const float* cW  = (const float*)d_in[9];
    const float* cb  = (const float*)d_in[10];
    const float* w21 = (const float*)d_in[11];
    const float* b21 = (const float*)d_in[12];
    const float* w22 = (const float*)d_in[13];
    const float* b22 = (const float*)d_in[14];
    const float* w23 = (const float*)d_in[15];
    const float* b23 = (const float*)d_in[16];
    const float* gamma = (const float*)d_in[17];
    const float* beta  = (const float*)d_in[18];
    float* out = (float*)d_out;

    cudaFuncSetAttribute(tconv_kernel,
                         cudaFuncAttributeMaxDynamicSharedMemorySize, TC_SMEM);

    // 1-3: prep (split so tconv1 is launch #4 = ncu window)
    prep_w_kernel<<<12, 256>>>(w11, w12, w13, 0);
    prep_w_kernel<<<12, 256>>>(w21, w22, w23, 1);
    prep_graph_kernel<<<1, 1024>>>(ei, ew);

    // 4: tconv1 (ncu window)
    {
        dim3 grid(Nv / 128, T1v, Bv);
        tconv_kernel<<<grid, 256, TC_SMEM>>>(x, b11, b12, b13, 0, 0, 0, Tv, T1v);
    }
    // 5: cheb GEMM (Y0, Y1)
    {
        dim3 grid(Nv / 128, T1v, Bv);
        cheb_gemm_kernel<<<grid, 256, CG_SMEM>>>(cW);
    }
    // 6: cheb gather
    {
        dim3 grid(Nv / 8, 16, Bv);
        cheb_gather_kernel<<<grid, 256>>>(cb);
    }
    // 7: tconv2
    {
        dim3 grid(Nv / 128, T2v, Bv);
        tconv_kernel<<<grid, 256, TC_SMEM>>>(x, b21, b22, b23, 1, 1, 1, T1v, T2v);
    }
    // 8: bn
    bn_kernel<<<Nv, 256>>>(gamma, beta, out);
}

// round 15
// speedup vs baseline: 1.1714x; 1.1714x over previous
#include <cuda_runtime.h>
#include <cuda_bf16.h>
#include <math.h>
#include <cstdint>

#define Bv   4
#define Tv   64
#define Nv   1024
#define Ev   16384
#define Cv   32
#define T1v  62
#define T2v  60

// ---- device scratch (referenced only from device code) ----
__device__ float g_h1[Bv * T1v * Nv * Cv];
__device__ float g_hc[Bv * T1v * Nv * Cv];
__device__ float g_h2[Bv * T2v * Nv * Cv];
__device__ float g_y0[Bv * T1v * Nv * Cv];
__device__ float g_y1[Bv * T1v * Nv * Cv];
__device__ unsigned g_wFh[2][4608];   // W bf16-hi, B-fragment order, N=96 packed gates
__device__ unsigned g_wFl[2][4608];   // W bf16-lo
__device__ int   g_rowptr[Nv + 1];
__device__ int   g_col[Ev];           // pre-multiplied by 32
__device__ float g_val[Ev];

// ---- f32x2 helpers (for cheb_gemm) ----
__device__ __forceinline__ unsigned long long fma2(unsigned long long a,
                                                   unsigned long long b,
                                                   unsigned long long c) {
    unsigned long long d;
    asm("fma.rn.f32x2 %0, %1, %2, %3;" : "=l"(d) : "l"(a), "l"(b), "l"(c));
    return d;
}
__device__ __forceinline__ unsigned long long dup2(float x) {
    unsigned long long d;
    unsigned u = __float_as_uint(x);
    asm("mov.b64 %0, {%1, %1};" : "=l"(d) : "r"(u));
    return d;
}
__device__ __forceinline__ void unpack2(unsigned long long v, float& lo, float& hi) {
    unsigned a, b;
    asm("mov.b64 {%0, %1}, %2;" : "=r"(a), "=r"(b) : "l"(v));
    lo = __uint_as_float(a);
    hi = __uint_as_float(b);
}

__device__ __forceinline__ unsigned pack_bf16(float a, float b) {
    unsigned short ua = __bfloat16_as_ushort(__float2bfloat16_rn(a));
    unsigned short ub = __bfloat16_as_ushort(__float2bfloat16_rn(b));
    return (unsigned)ua | ((unsigned)ub << 16);
}
__device__ __forceinline__ float bf16_hi_f(float a) {
    return __bfloat162float(__float2bfloat16_rn(a));
}

__device__ __forceinline__ void mma16816(float& d0, float& d1, float& d2, float& d3,
                                         unsigned a0, unsigned a1, unsigned a2, unsigned a3,
                                         unsigned b0, unsigned b1) {
    asm volatile(
        "mma.sync.aligned.m16n8k16.row.col.f32.bf16.bf16.f32 "
        "{%0,%1,%2,%3},{%4,%5,%6,%7},{%8,%9},{%0,%1,%2,%3};"
        : "+f"(d0), "+f"(d1), "+f"(d2), "+f"(d3)
        : "r"(a0), "r"(a1), "r"(a2), "r"(a3), "r"(b0), "r"(b1));
}

__device__ __forceinline__ void load_edge_f(const void* ei, int e, int is64,
                                            int& s, int& d) {
    if (is64) {
        const long long* e64 = (const long long*)ei;
        s = (int)e64[e]; d = (int)e64[Ev + e];
    } else {
        const int* e32 = (const int*)ei;
        s = e32[e]; d = e32[Ev + e];
    }
}

// ------------------------------------------------------------------
// Prep: W -> bf16 hi/lo B-fragments for mma.m16n8k16.
// B tile (kt,nt): 16k x 8n. Lane l: g=l>>2, tg=l&3.
// b0={B[2tg][g],B[2tg+1][g]}, b1={B[2tg+8][g],B[2tg+9][g]}.
// k index rx = ktplane*32+ci maps W[co*96 + ci*3 + ktplane]; col = gate*32+co.
// 4608 .b32 regs per plane per layer; dest (nt*6+ktile)*64 + lane*2 + reg.
// ------------------------------------------------------------------
__global__ void prep_wf_kernel(const float* __restrict__ wa, const float* __restrict__ wb,
                               const float* __restrict__ wc, int layer) {
    int i = blockIdx.x * blockDim.x + threadIdx.x;
    if (i >= 4608) return;
    int nt    = i / 384;
    int r     = i - nt * 384;
    int ktile = r >> 6;
    int r2    = r & 63;
    int lane  = r2 >> 1;
    int reg   = r2 & 1;
    int g  = lane >> 2;
    int tg = lane & 3;
    int cop  = nt * 8 + g;
    int gate = cop >> 5;
    int co   = cop & 31;
    int kl0  = 2 * tg + (reg ? 8 : 0);
    int rx0  = ktile * 16 + kl0;
    int rx1  = rx0 + 1;
    const float* ws = (gate == 0) ? wa : ((gate == 1) ? wb : wc);
    float w0 = ws[co * 96 + (rx0 & 31) * 3 + (rx0 >> 5)];
    float w1 = ws[co * 96 + (rx1 & 31) * 3 + (rx1 >> 5)];
    float h0 = bf16_hi_f(w0), h1 = bf16_hi_f(w1);
    int dest = (nt * 6 + ktile) * 64 + lane * 2 + reg;
    g_wFh[layer][dest] = pack_bf16(w0, w1);
    g_wFl[layer][dest] = pack_bf16(w0 - h0, w1 - h1);
}

// ------------------------------------------------------------------
// Prep: graph build (single block, 1024 threads, smem-resident).
// ------------------------------------------------------------------
__global__ void prep_graph_kernel(const void* __restrict__ ei,
                                  const float* __restrict__ ew) {
    __shared__ float sdeg[Nv];
    __shared__ int   scnt[Nv];
    __shared__ int   sscan[Nv];
    __shared__ int   soffs[Nv];
    __shared__ int   sOr;

    const int i = threadIdx.x;
    if (i == 0) sOr = 0;
    sdeg[i] = 0.f;
    scnt[i] = 0;
    __syncthreads();

    if (i < 128) {
        int v = ((const int*)ei)[2 * i + 1];
        if (v != 0) atomicOr(&sOr, 1);
    }
    __syncthreads();
    const int is64 = (sOr == 0) ? 1 : 0;

    for (int e = i; e < Ev; e += 1024) {
        int s, d;
        load_edge_f(ei, e, is64, s, d);
        if ((unsigned)s >= Nv || (unsigned)d >= Nv) continue;
        float w = ew[e];
        if (s != d) atomicAdd(&sdeg[s], w);
        atomicAdd(&scnt[d], 1);
    }
    __syncthreads();

    {
        float dg = sdeg[i];
        float dv = (dg > 0.f) ? rsqrtf(dg) : 0.f;
        __syncthreads();
        sdeg[i] = dv;
    }

    int c = scnt[i];
    sscan[i] = c;
    for (int off = 1; off < Nv; off <<= 1) {
        __syncthreads();
        int v = (i >= off) ? sscan[i - off] : 0;
        __syncthreads();
        sscan[i] += v;
    }
    __syncthreads();
    int excl = sscan[i] - c;
    g_rowptr[i] = excl;
    soffs[i]    = excl;
    if (i == Nv - 1) g_rowptr[Nv] = sscan[i];
    __syncthreads();

    for (int e = i; e < Ev; e += 1024) {
        int s, d;
        load_edge_f(ei, e, is64, s, d);
        if ((unsigned)s >= Nv || (unsigned)d >= Nv) continue;
        float w = ew[e];
        float nrm = (s == d) ? 0.f : (-sdeg[s] * w * sdeg[d]);
        int pos = atomicAdd(&soffs[d], 1);
        if ((unsigned)pos < Ev) {
            g_col[pos] = s * 32;
            g_val[pos] = nrm;
        }
    }
}

// ------------------------------------------------------------------
// Temporal gated conv via mma.sync bf16 3-pass (hi/lo split).
// Tile: 128 nodes (M) x 96 = 3 gates*32co (N), K = 96.
// Warp w: wm=w&3 (2 mtiles), wn=w>>2 (6 ntiles). 216 HMMA/warp.
// smem (.b32 units): Ah[0,6144) Al[6144,12288) Bh[12288,16896) Bl[16896,21504)
// stg overlay: floats [0, 128*98).
// ------------------------------------------------------------------
#define TC_SMEM (21504 * 4)

__global__ __launch_bounds__(256, 2)
void tconv_kernel(const float* __restrict__ xp,
                  const float* __restrict__ b1, const float* __restrict__ b2,
                  const float* __restrict__ b3,
                  int layer, int src_sel, int dst_sel, int Tin, int Tout)
{
    extern __shared__ __align__(16) unsigned smu[];
    unsigned* smAh = smu;
    unsigned* smAl = smu + 6144;
    unsigned* smBh = smu + 12288;
    unsigned* smBl = smu + 16896;

    const float* x   = (src_sel == 0) ? xp   : (const float*)g_hc;
    float*       out = (dst_sel == 0) ? g_h1 : g_h2;

    const int tid = threadIdx.x;
    const int n0  = blockIdx.x * 128;
    const int t   = blockIdx.y;
    const int b   = blockIdx.z;

    // W fragments: flat copy
    {
        const unsigned* wh = g_wFh[layer];
        const unsigned* wl = g_wFl[layer];
        for (int i = tid; i < 4608; i += 256) {
            smBh[i] = wh[i];
            smBl[i] = wl[i];
        }
    }
    // A fragments: read float2 (n, ci-pair), split hi/lo, pack, scatter-store
    {
        const float* xb = x + ((long long)(b * Tin + t) * Nv + n0) * Cv;
        for (int idx2 = tid; idx2 < 6144; idx2 += 256) {
            int kt  = idx2 >> 11;          // t-plane 0..2
            int rem = idx2 & 2047;
            int n   = rem >> 4;            // node 0..127
            int cip = rem & 15;            // ci pair 0..15
            float2 v = *(const float2*)(xb + (long long)kt * Nv * Cv + n * 32 + 2 * cip);
            int rx0   = kt * 32 + 2 * cip;
            int ktile = rx0 >> 4;
            int kl0   = rx0 & 15;
            int mtile = n >> 4;
            int rr    = n & 15;
            int lane  = ((rr & 7) << 2) | ((kl0 >> 1) & 3);
            int reg   = ((rr >> 3) & 1) | (((kl0 >> 3) & 1) << 1);
            int dest  = ((mtile * 6 + ktile) * 32 + lane) * 4 + reg;
            float h0 = bf16_hi_f(v.x), h1 = bf16_hi_f(v.y);
            smAh[dest] = pack_bf16(v.x, v.y);
            smAl[dest] = pack_bf16(v.x - h0, v.y - h1);
        }
    }
    __syncthreads();

    const int w    = tid >> 5;
    const int lane = tid & 31;
    const int wm   = w & 3;     // 2 mtiles: wm*2, wm*2+1
    const int wn   = w >> 2;    // 6 ntiles: wn*6 .. +5

    float d[2][6][4];
#pragma unroll
    for (int mt = 0; mt < 2; ++mt)
#pragma unroll
        for (int nt = 0; nt < 6; ++nt)
#pragma unroll
            for (int q = 0; q < 4; ++q) d[mt][nt][q] = 0.f;

    const unsigned* AP[3] = { smAh, smAl, smAh };
    const unsigned* BP[3] = { smBh, smBh, smBl };

#pragma unroll 1
    for (int p = 0; p < 3; ++p) {
        const unsigned* Ap = AP[p];
        const unsigned* Bp = BP[p];
#pragma unroll
        for (int kt = 0; kt < 6; ++kt) {
            uint4 a0 = *(const uint4*)(Ap + (((wm * 2 + 0) * 6 + kt) * 32 + lane) * 4);
            uint4 a1 = *(const uint4*)(Ap + (((wm * 2 + 1) * 6 + kt) * 32 + lane) * 4);
#pragma unroll
            for (int nt = 0; nt < 6; ++nt) {
                uint2 bb = *(const uint2*)(Bp + ((wn * 6 + nt) * 6 + kt) * 64 + lane * 2);
                mma16816(d[0][nt][0], d[0][nt][1], d[0][nt][2], d[0][nt][3],
                         a0.x, a0.y, a0.z, a0.w, bb.x, bb.y);
                mma16816(d[1][nt][0], d[1][nt][1], d[1][nt][2], d[1][nt][3],
                         a1.x, a1.y, a1.z, a1.w, bb.x, bb.y);
            }
        }
    }
    __syncthreads();   // smem reads done; overlay stg

    // stage D to stg[node][co'] (stride 98)
    {
        float* stg = (float*)smu;
        const int g  = lane >> 2;
        const int tg = lane & 3;
#pragma unroll
        for (int mt = 0; mt < 2; ++mt) {
            const int row0 = (wm * 2 + mt) * 16 + g;
#pragma unroll
            for (int nt = 0; nt < 6; ++nt) {
                const int col0 = (wn * 6 + nt) * 8 + 2 * tg;
                *(float2*)(stg + row0 * 98 + col0) =
                    make_float2(d[mt][nt][0], d[mt][nt][1]);
                *(float2*)(stg + (row0 + 8) * 98 + col0) =
                    make_float2(d[mt][nt][2], d[mt][nt][3]);
            }
        }
    }
    __syncthreads();

    // gated epilogue + write
    {
        const float* stg = (const float*)smu;
        float* ob = out + ((long long)(b * Tout + t) * Nv + n0) * Cv;
        for (int idx = tid; idx < 4096; idx += 256) {
            int node = idx >> 5, co = idx & 31;
            float p = stg[node * 98 + co]      + b1[co];
            float q = stg[node * 98 + 32 + co] + b2[co];
            float r = stg[node * 98 + 64 + co] + b3[co];
            float sg = 1.f / (1.f + __expf(-q));
            float h  = p * sg + r;
            ob[idx] = (h > 0.f) ? h : 0.f;
        }
    }
}

// ------------------------------------------------------------------
// Cheb GEMM: Y0 = h1 @ W0, Y1 = h1 @ W1 (proven R12 version).
// ------------------------------------------------------------------
#define CG_SMEM 33792

__global__ __launch_bounds__(256)
void cheb_gemm_kernel(const float* __restrict__ W)
{
    extern __shared__ __align__(16) float sm[];
    float* ws = sm;
    float* xs = sm + 2048;

    const int tid = threadIdx.x;
    const int n0  = blockIdx.x * 128;
    const int t   = blockIdx.y;
    const int b   = blockIdx.z;

    for (int i = tid; i < 2048; i += 256) {
        int k = i >> 6, o = i & 63;
        ws[i] = (o < 32) ? W[k * 32 + o] : W[1024 + k * 32 + (o - 32)];
    }
    {
        const float* xb = g_h1 + ((long long)(b * T1v + t) * Nv + n0) * Cv;
        for (int idx = tid; idx < 4096; idx += 256) {
            int n = idx >> 5, c = idx & 31;
            xs[c * 128 + (((n >> 2) ^ c) << 2) + (n & 3)] = xb[idx];
        }
    }
    __syncthreads();

    const int wg   = tid >> 5;
    const int lane = tid & 31;

    unsigned long long acc[16];
#pragma unroll
    for (int i = 0; i < 16; ++i) acc[i] = 0ull;

#pragma unroll 8
    for (int k = 0; k < 32; ++k) {
        const float4 xv4 = *(const float4*)(xs + k * 128 + ((lane ^ k) << 2));
        unsigned long long xp2[4];
        xp2[0] = dup2(xv4.x); xp2[1] = dup2(xv4.y);
        xp2[2] = dup2(xv4.z); xp2[3] = dup2(xv4.w);
        const float* wrow = ws + k * 64 + wg * 8;
        const ulonglong2 w01 = *(const ulonglong2*)(wrow);
        const ulonglong2 w23 = *(const ulonglong2*)(wrow + 4);
#pragma unroll
        for (int i = 0; i < 4; ++i) {
            acc[i * 4 + 0] = fma2(xp2[i], w01.x, acc[i * 4 + 0]);
            acc[i * 4 + 1] = fma2(xp2[i], w01.y, acc[i * 4 + 1]);
            acc[i * 4 + 2] = fma2(xp2[i], w23.x, acc[i * 4 + 2]);
            acc[i * 4 + 3] = fma2(xp2[i], w23.y, acc[i * 4 + 3]);
        }
    }
    __syncthreads();

    float* stg = sm;    // [128][66]
    const int nn = lane * 4;
#pragma unroll
    for (int i = 0; i < 4; ++i) {
#pragma unroll
        for (int p = 0; p < 4; ++p) {
            float lo, hi;
            unpack2(acc[i * 4 + p], lo, hi);
            *(float2*)(stg + (nn + i) * 66 + wg * 8 + p * 2) = make_float2(lo, hi);
        }
    }
    __syncthreads();

    const long long base = (long long)(b * T1v + t) * Nv * Cv + (long long)n0 * Cv;
    for (int idx = tid; idx < 4096; idx += 256) {
        int n = idx >> 5, c = idx & 31;
        g_y0[base + idx] = stg[n * 66 + c];
        g_y1[base + idx] = stg[n * 66 + 32 + c];
    }
}

// ------------------------------------------------------------------
// Cheb gather: out = relu(Y0[n] + cb + sum_e norm * Y1[src]).
// ------------------------------------------------------------------
__global__ __launch_bounds__(256)
void cheb_gather_kernel(const float* __restrict__ cbias)
{
    const int tid  = threadIdx.x;
    const int w    = tid >> 5;
    const int lane = tid & 31;
    const int b    = blockIdx.z;
    const int n    = blockIdx.x * 8 + w;
    const int t0   = blockIdx.y * 4;
    const int TC   = (t0 + 4 <= T1v) ? 4 : (T1v - t0);

    const float cb = __ldg(&cbias[lane]);
    const int e0 = g_rowptr[n], e1 = g_rowptr[n + 1];
    const long long stride = (long long)Nv * Cv;
    const float* base1 = g_y1 + (long long)(b * T1v + t0) * stride;
    const float* base0 = g_y0 + (long long)(b * T1v + t0) * stride;

    float lh[4] = {0.f, 0.f, 0.f, 0.f};

    int e = e0;
    for (; e + 2 <= e1; e += 2) {
        int   cA = g_col[e],   cB = g_col[e + 1];
        float vA = g_val[e],   vB = g_val[e + 1];
        const float* pA = base1 + cA + lane;
        const float* pB = base1 + cB + lane;
#pragma unroll
        for (int j = 0; j < 4; ++j) {
            if (j < TC) {
                lh[j] = fmaf(vA, pA[j * stride], lh[j]);
                lh[j] = fmaf(vB, pB[j * stride], lh[j]);
            }
        }
    }
    if (e < e1) {
        int   cA = g_col[e];
        float vA = g_val[e];
        const float* pA = base1 + cA + lane;
#pragma unroll
        for (int j = 0; j < 4; ++j)
            if (j < TC) lh[j] = fmaf(vA, pA[j * stride], lh[j]);
    }

    float* outb = g_hc + (long long)(b * T1v + t0) * stride + n * 32 + lane;
#pragma unroll
    for (int j = 0; j < 4; ++j) {
        if (j < TC) {
            float o = base0[j * stride + n * 32 + lane] + cb + lh[j];
            outb[j * stride] = (o > 0.f) ? o : 0.f;
        }
    }
}

// ------------------------------------------------------------------
// BatchNorm per node over (B, T2, C).
// ------------------------------------------------------------------
__global__ __launch_bounds__(256)
void bn_kernel(const float* __restrict__ gamma, const float* __restrict__ beta,
               float* __restrict__ outp)
{
    __shared__ float rs[256], rs2[256];
    __shared__ float s_scale, s_shift;
    const int n = blockIdx.x, tid = threadIdx.x;
    const int M = Bv * T2v * Cv;

    float s = 0.f, s2 = 0.f;
    for (int i = tid; i < M; i += 256) {
        int row = i >> 5, c = i & 31;
        float v = g_h2[((long long)row * Nv + n) * 32 + c];
        s += v; s2 += v * v;
    }
    rs[tid] = s; rs2[tid] = s2;
    __syncthreads();
    for (int off = 128; off > 0; off >>= 1) {
        if (tid < off) { rs[tid] += rs[tid + off]; rs2[tid] += rs2[tid + off]; }
        __syncthreads();
    }
    if (tid == 0) {
        float mean = rs[0] / (float)M;
        float var  = rs2[0] / (float)M - mean * mean;
        float rstd = rsqrtf(var + 1e-5f);
        float sc = gamma[n] * rstd;
        s_scale = sc;
        s_shift = beta[n] - mean * sc;
    }
    __syncthreads();
    const float sc = s_scale, sf = s_shift;
    for (int i = tid; i < M; i += 256) {
        int row = i >> 5, c = i & 31;
        long long idx = ((long long)row * Nv + n) * 32 + c;
        outp[idx] = g_h2[idx] * sc + sf;
    }
}

// ------------------------------------------------------------------
extern "C" void kernel_launch(void* const* d_in, const int* in_sizes, int n_in,
                              void* d_out, int out_size)
{
    const float* x   = (const float*)d_in[0];
    const void*  ei  = d_in[1];
    const float* ew  = (const float*)d_in[2];
    const float* w11 = (const float*)d_in[3];
    const float* b11 = (const float*)d_in[4];
    const float* w12 = (const float*)d_in[5];
    const float* b12 = (const float*)d_in[6];
    const float* w13 = (const float*)d_in[7];
    const float* b13 = (const float*)d_in[8];
    const float* cW  = (const float*)d_in[9];
    const float* cb  = (const float*)d_in[10];
    const float* w21 = (const float*)d_in[11];
    const float* b21 = (const float*)d_in[12];
    const float* w22 = (const float*)d_in[13];
    const float* b22 = (const float*)d_in[14];
    const float* w23 = (const float*)d_in[15];
    const float* b23 = (const float*)d_in[16];
    const float* gamma = (const float*)d_in[17];
    const float* beta  = (const float*)d_in[18];
    float* out = (float*)d_out;

    cudaFuncSetAttribute(tconv_kernel,
                         cudaFuncAttributeMaxDynamicSharedMemorySize, TC_SMEM);

    // 1-3: prep (tconv1 stays launch #4 = ncu window)
    prep_wf_kernel<<<18, 256>>>(w11, w12, w13, 0);
    prep_wf_kernel<<<18, 256>>>(w21, w22, w23, 1);
    prep_graph_kernel<<<1, 1024>>>(ei, ew);

    // 4: tconv1 (tensor path)
    {
        dim3 grid(Nv / 128, T1v, Bv);
        tconv_kernel<<<grid, 256, TC_SMEM>>>(x, b11, b12, b13, 0, 0, 0, Tv, T1v);
    }
    // 5: cheb GEMM
    {
        dim3 grid(Nv / 128, T1v, Bv);
        cheb_gemm_kernel<<<grid, 256, CG_SMEM>>>(cW);
    }
    // 6: cheb gather
    {
        dim3 grid(Nv / 8, 16, Bv);
        cheb_gather_kernel<<<grid, 256>>>(cb);
    }
    // 7: tconv2 (tensor path)
    {
        dim3 grid(Nv / 128, T2v, Bv);
        tconv_kernel<<<grid, 256, TC_SMEM>>>(x, b21, b22, b23, 1, 1, 1, T1v, T2v);
    }
    // 8: bn
    bn_kernel<<<Nv, 256>>>(gamma, beta, out);
}